// round 7
// baseline (speedup 1.0000x reference)
#include <cuda_runtime.h>

// CoincidenceLIFBank: B=32 x T=4096 x D=256.
// Output: [0,B*D) pooled | [B*D,+B*D*T) spikes | +D rw | +D tw | +D beta
//
// NUMERICS FROZEN (passed R6, rel_err 9.89e-4):
//  - params: softplus = max(x,0) + NAIVE log(1+exp(-|x|)); sigmoid = 1/(1+exp(-x));
//    beta = 0.7 + 0.295*sigmoid (uncontracted). All bit-exact vs reference.
//  - scan: cur = fadd(fmul(rw,rv), fmul(tw,tv))  [UNcontracted]
//          mp  = fma(beta, m, cur)               [contracted]
//          ms  = fadd(mp, -1)  (exact);  m = p ? ms : mp;  s = p ? 1 : 0.
// This round changes ONLY control flow / scheduling, not values.

#define NB 32
#define NT 4096
#define ND 256
#define THRESH 1.0f
#define UNROLL 16

__device__ __forceinline__ float softplus_xla(float x) {
    const float u = expf(-fabsf(x));
    return __fadd_rn(fmaxf(x, 0.0f), logf(__fadd_rn(1.0f, u)));
}
__device__ __forceinline__ float sigmoid_xla(float x) {
    return 1.0f / (__fadd_rn(1.0f, expf(-x)));
}

__global__ void __launch_bounds__(64)
lif_bank_kernel(const float* __restrict__ ref,
                const float* __restrict__ tgt,
                const int*   __restrict__ delays,
                const float* __restrict__ rw_raw,
                const float* __restrict__ tw_raw,
                const float* __restrict__ beta_raw,
                float* __restrict__ out)
{
    const int tid = blockIdx.x * 64 + threadIdx.x;   // 0..8191
    const int d = tid & (ND - 1);
    const int b = tid >> 8;

    const float rw   = softplus_xla(rw_raw[d]);
    const float tw   = softplus_xla(tw_raw[d]);
    const float beta = __fadd_rn(0.7f, __fmul_rn(0.295f, sigmoid_xla(beta_raw[d])));
    const int   delay = delays[d];
    const int   tmax  = NT - delay;        // t < tmax -> delayed ref valid
    const int   tclamp = tmax - 1;         // max in-bounds offset into refrow

    const float* __restrict__ refrow = ref + b * NT + delay;
    const float* __restrict__ tgtrow = tgt + b * NT;

    float* out_pooled = out;
    float* out_spk    = out + NB * ND;
    float* out_rw     = out + NB * ND + (size_t)NB * ND * NT;
    float* out_tw     = out_rw + ND;
    float* out_beta   = out_tw + ND;

    float* __restrict__ spk = out_spk + (size_t)(b * ND + d) * NT;

    float m = 0.0f;
    float cnt = 0.0f;

    for (int t0 = 0; t0 < NT; t0 += UNROLL) {
        // ---- off-chain: gather inputs + precompute cur[] (branch-free) ----
        float tv[UNROLL];
#pragma unroll
        for (int q = 0; q < UNROLL / 4; q++) {
            const float4 v = __ldg((const float4*)(tgtrow + t0 + 4 * q));
            tv[4 * q + 0] = v.x; tv[4 * q + 1] = v.y;
            tv[4 * q + 2] = v.z; tv[4 * q + 3] = v.w;
        }

        float cur[UNROLL];
#pragma unroll
        for (int j = 0; j < UNROLL; j++) {
            const int t = t0 + j;
            // unconditional clamped load (no divergence, always in-bounds),
            // then FSEL-zero past the valid range. Same VALUE as before.
            const float rraw = __ldg(refrow + min(t, tclamp));
            const float rv   = (t < tmax) ? rraw : 0.0f;
            cur[j] = __fadd_rn(__fmul_rn(rw, rv), __fmul_rn(tw, tv[j]));
        }

        // ---- serial LIF chain: FMA -> {FADD || FSETP} -> FSEL per step ----
        float sp[UNROLL];
#pragma unroll
        for (int j = 0; j < UNROLL; j++) {
            const float mp = __fmaf_rn(beta, m, cur[j]);
            const float ms = __fadd_rn(mp, -THRESH);
            const bool  p  = (mp >= THRESH);
            m = p ? ms : mp;
            sp[j] = p ? 1.0f : 0.0f;
            cnt += sp[j];
        }

        // ---- off-chain: full-sector store bursts (4 x STG.128 = 64B) ----
#pragma unroll
        for (int q = 0; q < UNROLL / 4; q++) {
            *(float4*)(spk + t0 + 4 * q) =
                make_float4(sp[4*q+0], sp[4*q+1], sp[4*q+2], sp[4*q+3]);
        }
    }

    out_pooled[b * ND + d] = cnt * (1.0f / NT);

    if (b == 0) {
        out_rw[d]   = rw;
        out_tw[d]   = tw;
        out_beta[d] = beta;
    }
}

extern "C" void kernel_launch(void* const* d_in, const int* in_sizes, int n_in,
                              void* d_out, int out_size)
{
    const float* ref      = (const float*)d_in[0];
    const float* tgt      = (const float*)d_in[1];
    const int*   delays   = (const int*)  d_in[2];
    const float* rw_raw   = (const float*)d_in[3];
    const float* tw_raw   = (const float*)d_in[4];
    const float* beta_raw = (const float*)d_in[5];
    float* out = (float*)d_out;

    // 8192 sequences, 1 thread each. block=64 -> each warp lands on its own
    // SMSP (no SMSP-0 pileup from multiple 1-warp blocks per SM); grid=128
    // blocks over 148 SMs, single wave.
    lif_bank_kernel<<<(NB * ND) / 64, 64>>>(ref, tgt, delays, rw_raw, tw_raw,
                                            beta_raw, out);
}

// round 9
// speedup vs baseline: 1.3771x; 1.3771x over previous
#include <cuda_runtime.h>

// CoincidenceLIFBank: B=32 x T=4096 x D=256.
// Output: [0,B*D) pooled | [B*D,+B*D*T) spikes | +D rw | +D tw | +D beta
//
// NUMERICS FROZEN (passed R6, rel_err 9.89e-4):
//   rw/tw = max(x,0) + logf(1 + expf(-|x|));  sigmoid = 1/(1+expf(-x))
//   beta  = fadd(0.7, fmul(0.295, sigmoid))           (uncontracted)
//   cur   = fadd(fmul(rw, rv), fmul(tw, tv))          (UNcontracted)
//   mp    = fma(beta, m, cur);  ms = fadd(mp,-1); p = (mp>=1)
//   m = p ? ms : mp;  s = p ? 1 : 0
// This round: data movement only. R8's misalignment fixed: tile row stride
// 132 floats (528B, 16B multiple). All smem 128b accesses run at the 4-phase
// crossbar bandwidth floor.

#define NB 32
#define NT 4096
#define ND 256
#define THRESH 1.0f
#define TILE 128               // timesteps buffered per dump
#define TSTRIDE 132            // floats per tile row (16B-aligned, bank-spread)

__device__ __forceinline__ float softplus_xla(float x) {
    const float u = expf(-fabsf(x));
    return __fadd_rn(fmaxf(x, 0.0f), logf(__fadd_rn(1.0f, u)));
}
__device__ __forceinline__ float sigmoid_xla(float x) {
    return 1.0f / (__fadd_rn(1.0f, expf(-x)));
}

__global__ void __launch_bounds__(32)
lif_bank_kernel(const float* __restrict__ ref,
                const float* __restrict__ tgt,
                const int*   __restrict__ delays,
                const float* __restrict__ rw_raw,
                const float* __restrict__ tw_raw,
                const float* __restrict__ beta_raw,
                float* __restrict__ out)
{
    // 256 single-warp blocks. Block -> (b, d0): 8 blocks per batch row.
    const int lane = threadIdx.x;
    const int b    = blockIdx.x >> 3;
    const int d0   = (blockIdx.x & 7) * 32;
    const int d    = d0 + lane;

    __shared__ float sref[NT];                 // ref[b,:] staged (16 KB)
    __shared__ float stile[32][TSTRIDE];       // spike transpose tile (16.5 KB)

    // ---- stage ref row: 32 x warp-wide LDG.128, fully coalesced ----
    {
        const float4* __restrict__ ref4 = (const float4*)(ref + b * NT);
        float4* sref4 = (float4*)sref;
#pragma unroll
        for (int i = 0; i < NT / 4 / 32; i++)
            sref4[lane + 32 * i] = __ldg(ref4 + lane + 32 * i);
    }

    // ---- per-bank params (frozen recipe) ----
    const float rw   = softplus_xla(rw_raw[d]);
    const float tw   = softplus_xla(tw_raw[d]);
    const float beta = __fadd_rn(0.7f, __fmul_rn(0.295f, sigmoid_xla(beta_raw[d])));
    const int   delay = delays[d];

    const float* __restrict__ tgtrow = tgt + b * NT;

    float* out_pooled = out;
    float* out_spk    = out + NB * ND;
    float* out_rw     = out + NB * ND + (size_t)NB * ND * NT;
    float* out_tw     = out_rw + ND;
    float* out_beta   = out_tw + ND;

    float m = 0.0f;
    float cnt = 0.0f;

    __syncwarp();   // sref visible warp-wide

    for (int tile0 = 0; tile0 < NT; tile0 += TILE) {
        // ================= scan phase: TILE steps =================
        for (int t0 = tile0; t0 < tile0 + TILE; t0 += 4) {
            // off-chain: tgt (warp-uniform float4 broadcast)
            const float4 v = __ldg((const float4*)(tgtrow + t0));
            const float tv[4] = {v.x, v.y, v.z, v.w};

            // off-chain: ref from smem (clamped index, FSEL-zero OOB)
            float cur[4];
#pragma unroll
            for (int j = 0; j < 4; j++) {
                const int idx = delay + t0 + j;
                const float rr = sref[min(idx, NT - 1)];
                const float rv = (idx < NT) ? rr : 0.0f;
                cur[j] = __fadd_rn(__fmul_rn(rw, rv), __fmul_rn(tw, tv[j]));
            }

            // serial chain: FMA -> {FADD || FSETP} -> FSEL per step
            float sp[4];
#pragma unroll
            for (int j = 0; j < 4; j++) {
                const float mp = __fmaf_rn(beta, m, cur[j]);
                const float ms = __fadd_rn(mp, -THRESH);
                const bool  p  = (mp >= THRESH);
                m = p ? ms : mp;
                sp[j] = p ? 1.0f : 0.0f;
                cnt += sp[j];
            }

            // one STS.128 per 4 steps (bandwidth-floor 4-phase)
            *(float4*)&stile[lane][t0 - tile0] =
                make_float4(sp[0], sp[1], sp[2], sp[3]);
        }
        __syncwarp();

        // ====== dump: 32 rows x 512B contiguous STG.128 bursts ======
#pragma unroll 4
        for (int r = 0; r < 32; r++) {
            const float4 w = *(const float4*)&stile[r][lane * 4];
            float* dst = out_spk + (size_t)(b * ND + d0 + r) * NT + tile0;
            *(float4*)(dst + lane * 4) = w;
        }
        __syncwarp();
    }

    out_pooled[b * ND + d] = cnt * (1.0f / NT);

    if (b == 0) {   // blocks 0..7 cover d = 0..255 exactly once
        out_rw[d]   = rw;
        out_tw[d]   = tw;
        out_beta[d] = beta;
    }
}

extern "C" void kernel_launch(void* const* d_in, const int* in_sizes, int n_in,
                              void* d_out, int out_size)
{
    const float* ref      = (const float*)d_in[0];
    const float* tgt      = (const float*)d_in[1];
    const int*   delays   = (const int*)  d_in[2];
    const float* rw_raw   = (const float*)d_in[3];
    const float* tw_raw   = (const float*)d_in[4];
    const float* beta_raw = (const float*)d_in[5];
    float* out = (float*)d_out;

    // 256 single-warp blocks (one per (b, 32-d-group)); ~33 KB smem each.
    lif_bank_kernel<<<NB * 8, 32>>>(ref, tgt, delays, rw_raw, tw_raw,
                                    beta_raw, out);
}